// round 8
// baseline (speedup 1.0000x reference)
#include <cuda_runtime.h>
#include <cstdint>

#define FULL_MASK 0xffffffffu

// scratch: K-major transposed projections (tf32, k-permuted per 8-group) and wf
__device__ float g_Lt[8192 * 128];   // [col = n*32 + x][m permuted]
__device__ float g_Rt[8192 * 128];   // [col = n*32 + y][m permuted]
__device__ float g_wfT[128 * 1024];  // [o][k permuted]

// ------------------------- helpers -------------------------
__device__ __forceinline__ uint32_t smem_u32(const void *p) {
    uint32_t a;
    asm("{ .reg .u64 t; cvta.to.shared.u64 t, %1; cvt.u32.u64 %0, t; }"
        : "=r"(a) : "l"(p));
    return a;
}
__device__ __forceinline__ uint32_t to_tf32(float f) {
    uint32_t u;
    asm("cvt.rna.tf32.f32 %0, %1;" : "=r"(u) : "f"(f));
    return u;
}
__device__ __forceinline__ void cpa16(uint32_t dst, const void *src) {
    asm volatile("cp.async.ca.shared.global [%0], [%1], 16;"
                 :: "r"(dst), "l"(src));
}
#define CP_COMMIT() asm volatile("cp.async.commit_group;" ::: "memory")
#define CP_WAIT(n) asm volatile("cp.async.wait_group %0;" :: "n"(n) : "memory")

__device__ __forceinline__ void mma8(float *c, uint2 a01, uint2 a23, uint2 b) {
    asm volatile(
        "mma.sync.aligned.m16n8k8.row.col.f32.tf32.tf32.f32 "
        "{%0,%1,%2,%3}, {%4,%5,%6,%7}, {%8,%9}, {%0,%1,%2,%3};"
        : "+f"(c[0]), "+f"(c[1]), "+f"(c[2]), "+f"(c[3])
        : "r"(a01.x), "r"(a23.x), "r"(a01.y), "r"(a23.y),
          "r"(b.x), "r"(b.y));
}

// k-permutation within 8-groups: pos(k) = (k&~7) + (k&3)*2 + ((k>>2)&1)
// inverse within group: d(e) = (e>>1) + 4*(e&1)

// =====================================================================
// Kernel 0: transpose wf [1024][128] -> g_wfT [128][1024] (tf32, permuted)
// =====================================================================
__global__ __launch_bounds__(256) void k0_wft(const float *__restrict__ wf) {
    __shared__ float Tk[32 * 130];
    const int t = threadIdx.x;
    const int b = blockIdx.x;  // k-chunk 0..31
#pragma unroll
    for (int it = 0; it < 16; it++) {
        int f = t + it * 256;       // 0..4095
        int kk = f >> 7, o = f & 127;
        Tk[kk * 130 + o] = wf[(size_t)(b * 32 + kk) * 128 + o];
    }
    __syncthreads();
#pragma unroll
    for (int it = 0; it < 4; it++) {
        int f4 = t + it * 256;      // 0..1023
        int o = f4 >> 3, kq = f4 & 7;
        uint4 v;
        uint32_t *vv = (uint32_t *)&v;
#pragma unroll
        for (int e4 = 0; e4 < 4; e4++) {
            int e = (kq & 1) * 4 + e4;
            int d = (e >> 1) + 4 * (e & 1);
            int kk = (kq >> 1) * 8 + d;  // local k 0..31
            vv[e4] = to_tf32(Tk[kk * 130 + o]);
        }
        *(uint4 *)(g_wfT + (size_t)o * 1024 + b * 32 + kq * 4) = v;
    }
}

// =====================================================================
// Kernel 1: LayerNorm + projections -> g_Lt/g_Rt (tf32, m-permuted)
// grid = 1024: block b -> mc = b>>8 (m-chunk of 32), n = b&255.
// =====================================================================
__global__ __launch_bounds__(256) void k1_ln_proj(
    const float *__restrict__ x, const float *__restrict__ mask,
    const float *__restrict__ norm_w, const float *__restrict__ norm_b,
    const float *__restrict__ wl, const float *__restrict__ bl,
    const float *__restrict__ wr, const float *__restrict__ br) {
    extern __shared__ float sm[];
    float *sw = sm;           // [256][64]
    float *sb = sw + 16384;   // [64]
    float *snw = sb + 64;     // [256]
    float *snb = snw + 256;   // [256]
    float *sxn = snb + 256;   // [32][256] (reused as T[64][36])

    const int t = threadIdx.x;
    for (int idx = t; idx < 16384; idx += 256) {
        int k = idx >> 6, c = idx & 63;
        sw[idx] = (c < 32) ? wl[k * 32 + c] : wr[k * 32 + c - 32];
    }
    if (t < 64) sb[t] = (t < 32) ? bl[t] : br[t - 32];
    snw[t] = norm_w[t];
    snb[t] = norm_b[t];
    __syncthreads();

    const int mc = blockIdx.x >> 8;
    const int n = blockIdx.x & 255;

    {
        const int warp = t >> 5, lane = t & 31;
#pragma unroll
        for (int rr = 0; rr < 4; rr++) {
            const int lrow = warp * 4 + rr;
            const int m = mc * 32 + lrow;
            const float4 *xr = (const float4 *)(x + ((size_t)m * 256 + n) * 256);
            float4 v0 = xr[lane];
            float4 v1 = xr[32 + lane];
            float s1 = v0.x + v0.y + v0.z + v0.w + v1.x + v1.y + v1.z + v1.w;
            float s2 = v0.x * v0.x + v0.y * v0.y + v0.z * v0.z + v0.w * v0.w +
                       v1.x * v1.x + v1.y * v1.y + v1.z * v1.z + v1.w * v1.w;
#pragma unroll
            for (int off = 16; off; off >>= 1) {
                s1 += __shfl_xor_sync(FULL_MASK, s1, off);
                s2 += __shfl_xor_sync(FULL_MASK, s2, off);
            }
            float mu = s1 * (1.f / 256.f);
            float var = s2 * (1.f / 256.f) - mu * mu;
            float inv = rsqrtf(var + 1e-5f);
            int k0 = lane * 4, k1i = 128 + lane * 4;
            float4 n0, n1;
            n0.x = (v0.x - mu) * inv * snw[k0 + 0] + snb[k0 + 0];
            n0.y = (v0.y - mu) * inv * snw[k0 + 1] + snb[k0 + 1];
            n0.z = (v0.z - mu) * inv * snw[k0 + 2] + snb[k0 + 2];
            n0.w = (v0.w - mu) * inv * snw[k0 + 3] + snb[k0 + 3];
            n1.x = (v1.x - mu) * inv * snw[k1i + 0] + snb[k1i + 0];
            n1.y = (v1.y - mu) * inv * snw[k1i + 1] + snb[k1i + 1];
            n1.z = (v1.z - mu) * inv * snw[k1i + 2] + snb[k1i + 2];
            n1.w = (v1.w - mu) * inv * snw[k1i + 3] + snb[k1i + 3];
            ((float4 *)(sxn + lrow * 256))[lane] = n0;
            ((float4 *)(sxn + lrow * 256))[32 + lane] = n1;
        }
    }
    __syncthreads();

    const int tr = t >> 5;
    const int c2 = t & 31;
    float2 acc[4] = {{0, 0}, {0, 0}, {0, 0}, {0, 0}};
    const float *xr0 = sxn + tr * 4 * 256;
#pragma unroll 8
    for (int k = 0; k < 256; k++) {
        float2 wv = *(const float2 *)(sw + k * 64 + c2 * 2);
#pragma unroll
        for (int i = 0; i < 4; i++) {
            float a = xr0[i * 256 + k];
            acc[i].x = fmaf(a, wv.x, acc[i].x);
            acc[i].y = fmaf(a, wv.y, acc[i].y);
        }
    }
    float2 bv = *(const float2 *)(sb + c2 * 2);
    float2 ov[4];
#pragma unroll
    for (int i = 0; i < 4; i++) {
        int m = mc * 32 + tr * 4 + i;
        float mv = mask[m * 256 + n];
        ov[i].x = (acc[i].x + bv.x) * mv;
        ov[i].y = (acc[i].y + bv.y) * mv;
    }
    __syncthreads();
    float *T = sxn;  // [64][36]
    {
        int ch = (c2 < 16) ? (c2 * 2) : (32 + (c2 - 16) * 2);
#pragma unroll
        for (int i = 0; i < 4; i++) {
            int ml = tr * 4 + i;
            T[ch * 36 + ml] = ov[i].x;
            T[(ch + 1) * 36 + ml] = ov[i].y;
        }
    }
    __syncthreads();
    {
        int ch = t >> 2;
        int m0 = (t * 8) & 31;   // group-aligned (0,8,16,24)
        float v[8];
#pragma unroll
        for (int d = 0; d < 8; d++) v[d] = T[ch * 36 + m0 + d];
        // permuted store: position e holds d(e) = (e>>1)+4*(e&1)
        uint4 q0, q1;
        q0.x = to_tf32(v[0]); q0.y = to_tf32(v[4]);
        q0.z = to_tf32(v[1]); q0.w = to_tf32(v[5]);
        q1.x = to_tf32(v[2]); q1.y = to_tf32(v[6]);
        q1.z = to_tf32(v[3]); q1.w = to_tf32(v[7]);
        float *dst = ((ch < 32) ? g_Lt : g_Rt) +
                     (size_t)(n * 32 + (ch & 31)) * 128 + mc * 32 + m0;
        *(uint4 *)dst = q0;
        *(uint4 *)(dst + 4) = q1;
    }
}

// =====================================================================
// Kernel 2: fused outer-product (stage B) + projection (stage C), tf32 HMMA
// grid = (64, 32): CTA (bi, bj2): i-block bi (128 ix), j-blocks jb=bj2*2+g.
// Pipelined: ONE __syncthreads per chunk; stage C uses 3 cp.async buffers.
// =====================================================================
// smem layout (bytes):
//   0      : snorm[32] floats
//   1024   : stage B: buf0 (A 18432 | B 18432); stage C: cbuf0 / cbuf1
//   37888  : stage B: buf1 (A 18432 | B 18432); stage C: cbuf2
//   75776  : S' [32 p][1028 floats] stride 4112B   (131584 B)
// total 207360
#define OFF_SP 75776
#define SP_STRIDE 4112
#define TROW 144

__global__ __launch_bounds__(256, 1) void k2_opm(
    const float *__restrict__ mask, const float *__restrict__ bf,
    float *__restrict__ out) {
    extern __shared__ __align__(1024) char smem[];
    const uint32_t sb32 = smem_u32(smem);
    const int t = threadIdx.x, w = t >> 5, lane = t & 31;
    const int rb = lane >> 2, q = lane & 3;
    const int bi = blockIdx.x, bj2 = blockIdx.y;
    float *snorm = (float *)smem;
    const int OA[2] = {1024, 37888};
    const int CB[3] = {1024, 19456, 37888};

    // ---- pair norms ----
    {
        int p = t >> 3, l = t & 7;
        int g = p >> 4, ii = (p >> 2) & 3, jj = p & 3;
        int gi = bi * 4 + ii, gj = (bj2 * 2 + g) * 4 + jj;
        float s = 0.f;
#pragma unroll
        for (int mm = 0; mm < 16; mm++) {
            int m = l + mm * 8;
            s += mask[m * 256 + gi] * mask[m * 256 + gj];
        }
        s += __shfl_down_sync(FULL_MASK, s, 4);
        s += __shfl_down_sync(FULL_MASK, s, 2);
        s += __shfl_down_sync(FULL_MASK, s, 1);
        if (l == 0) snorm[p] = s;
    }

    // ================= Stage B =================
    // chunk loader: A = R rows (jy), B = L rows (ix); 128 rows x 32 m-k each
    auto loadB = [&](int buf, int g, int mcv) {
        int jb = bj2 * 2 + g;
        uint32_t dA = sb32 + OA[buf], dB = dA + 18432;
#pragma unroll
        for (int i = 0; i < 4; i++) {
            int u = t + i * 256;          // 16B unit 0..1023
            int row = u >> 3, qq = u & 7;
            cpa16(dA + row * TROW + qq * 16,
                  g_Rt + (size_t)(jb * 128 + row) * 128 + mcv * 32 + qq * 4);
            cpa16(dB + row * TROW + qq * 16,
                  g_Lt + (size_t)(bi * 128 + row) * 128 + mcv * 32 + qq * 4);
        }
    };

    const int wm = w >> 1, wn = w & 1;  // warp tile: M rows jy 32, N cols ix 64
    loadB(0, 0, 0);
    CP_COMMIT();

    for (int g = 0; g < 2; g++) {
        float acc[2][8][4];
#pragma unroll
        for (int a = 0; a < 2; a++)
#pragma unroll
            for (int b = 0; b < 8; b++)
#pragma unroll
                for (int c = 0; c < 4; c++) acc[a][b][c] = 0.f;

        for (int mcv = 0; mcv < 4; mcv++) {
            const int c = g * 4 + mcv, buf = c & 1;
            CP_WAIT(0);
            __syncthreads();  // chunk c ready; all warps done with chunk c-1
            if (c < 7) {
                int nc = c + 1;
                loadB(nc & 1, nc >> 2, nc & 3);  // overwrites buf consumed @ c-1
                CP_COMMIT();
            }
            const char *A = smem + OA[buf];
            const char *B = smem + OA[buf] + 18432;
#pragma unroll
            for (int s = 0; s < 4; s++) {
                uint2 afr[2][2];
#pragma unroll
                for (int mt = 0; mt < 2; mt++) {
                    int r = wm * 32 + mt * 16 + rb;
                    afr[mt][0] = *(const uint2 *)(A + r * TROW + s * 32 + q * 8);
                    afr[mt][1] =
                        *(const uint2 *)(A + (r + 8) * TROW + s * 32 + q * 8);
                }
#pragma unroll
                for (int nt = 0; nt < 8; nt++) {
                    int n = wn * 64 + nt * 8 + rb;
                    uint2 b = *(const uint2 *)(B + n * TROW + s * 32 + q * 8);
                    mma8(acc[0][nt], afr[0][0], afr[0][1], b);
                    mma8(acc[1][nt], afr[1][0], afr[1][1], b);
                }
            }
        }
        // write S'_g (tf32-rounded), permuted k positions.
        // No sync needed: S' region disjoint from bufs; per-thread targets.
#pragma unroll
        for (int mt = 0; mt < 2; mt++)
#pragma unroll
            for (int nt = 0; nt < 8; nt++)
#pragma unroll
                for (int cr = 0; cr < 4; cr++) {
                    int jy = wm * 32 + mt * 16 + rb + ((cr >= 2) ? 8 : 0);
                    int ix = wn * 64 + nt * 8 + q * 2 + (cr & 1);
                    int p = g * 16 + (ix >> 5) * 4 + (jy >> 5);
                    int k = (ix & 31) * 32 + (jy & 31);
                    int pos = (k & ~7) + (k & 3) * 2 + ((k >> 2) & 1);
                    *(uint32_t *)(smem + OFF_SP + p * SP_STRIDE + pos * 4) =
                        to_tf32(acc[mt][nt][cr]);
                }
    }

    // ================= Stage C =================
    // out^T[o 128][p 32] = sum_k wfT[o][k] * S'[p][k]; warp w: M tile o=w*16
    auto loadC = [&](int buf, int ct) {
        uint32_t dA = sb32 + CB[buf];
#pragma unroll
        for (int i = 0; i < 4; i++) {
            int u = t + i * 256;          // 16B unit 0..1023 (128 rows x 8)
            int row = u >> 3, qq = u & 7;
            cpa16(dA + row * TROW + qq * 16,
                  g_wfT + (size_t)row * 1024 + ct * 32 + qq * 4);
        }
    };

    // Prefetch chunks 0,1. Safe vs stage B: last compute (chunk 7) read
    // OA[1]=37888..; S' writes are disjoint. CB0/CB1 live in [1024,37888),
    // whose last readers (chunk 6) were sync-fenced at top of chunk 7.
    loadC(0, 0);
    CP_COMMIT();
    loadC(1, 1);
    CP_COMMIT();

    float cc[4][4];
#pragma unroll
    for (int a = 0; a < 4; a++)
#pragma unroll
        for (int b = 0; b < 4; b++) cc[a][b] = 0.f;

    for (int ct = 0; ct < 32; ct++) {
        const int buf = ct - (ct / 3) * 3;  // ct % 3
        if (ct < 31) { CP_WAIT(1); } else { CP_WAIT(0); }
        __syncthreads();  // buf[ct%3] ready; all warps done with ct-1
        if (ct + 2 < 32) {
            int nb = (ct + 2) - ((ct + 2) / 3) * 3;
            loadC(nb, ct + 2);  // overwrites buf consumed @ ct-1
            CP_COMMIT();
        }
        const char *A = smem + CB[buf];
#pragma unroll
        for (int s = 0; s < 4; s++) {
            int r = w * 16 + rb;
            uint2 a0 = *(const uint2 *)(A + r * TROW + s * 32 + q * 8);
            uint2 a1 = *(const uint2 *)(A + (r + 8) * TROW + s * 32 + q * 8);
#pragma unroll
            for (int nt = 0; nt < 4; nt++) {
                int n = nt * 8 + rb;
                uint2 b = *(const uint2 *)(smem + OFF_SP + n * SP_STRIDE +
                                           (ct * 32 + s * 8 + q * 2) * 4);
                mma8(cc[nt], a0, a1, b);
            }
        }
    }
    __syncthreads();  // all compute done; buffer region reusable for sOut

    // ---- epilogue: stage through smem, bias + norm, coalesced store ----
    float *sOut = (float *)(smem + CB[0]);  // [32 p][128 o]
#pragma unroll
    for (int nt = 0; nt < 4; nt++)
#pragma unroll
        for (int cr = 0; cr < 4; cr++) {
            int o = w * 16 + rb + ((cr >= 2) ? 8 : 0);
            int p = nt * 8 + q * 2 + (cr & 1);
            sOut[p * 128 + o] = cc[nt][cr];
        }
    __syncthreads();
#pragma unroll
    for (int i = 0; i < 4; i++) {
        int u = t + i * 256;          // float4 unit 0..1023
        int p = u >> 5, o4 = (u & 31) * 4;
        int g = p >> 4, iiv = (p >> 2) & 3, jjv = p & 3;
        int gi = bi * 4 + iiv, gj = (bj2 * 2 + g) * 4 + jjv;
        float inv = 1.f / (snorm[p] + 0.001f);
        float4 v = *(float4 *)(sOut + p * 128 + o4);
        float4 bb = *(const float4 *)(bf + o4);
        v.x = (v.x + bb.x) * inv;
        v.y = (v.y + bb.y) * inv;
        v.z = (v.z + bb.z) * inv;
        v.w = (v.w + bb.w) * inv;
        *(float4 *)(out + ((size_t)gi * 256 + gj) * 128 + o4) = v;
    }
}

// =====================================================================
extern "C" void kernel_launch(void *const *d_in, const int *in_sizes, int n_in,
                              void *d_out, int out_size) {
    const float *x = (const float *)d_in[0];
    const float *mask = (const float *)d_in[1];
    const float *norm_w = (const float *)d_in[2];
    const float *norm_b = (const float *)d_in[3];
    const float *wl = (const float *)d_in[4];
    const float *bl = (const float *)d_in[5];
    const float *wr = (const float *)d_in[6];
    const float *br = (const float *)d_in[7];
    const float *wf = (const float *)d_in[8];
    const float *bf = (const float *)d_in[9];
    float *out = (float *)d_out;

    const int smem1 = (16384 + 64 + 256 + 256 + 8192) * 4;  // 100608 B
    const int smem2 = 207360;
    cudaFuncSetAttribute(k1_ln_proj, cudaFuncAttributeMaxDynamicSharedMemorySize, smem1);
    cudaFuncSetAttribute(k2_opm, cudaFuncAttributeMaxDynamicSharedMemorySize, smem2);

    k0_wft<<<32, 256>>>(wf);
    k1_ln_proj<<<1024, 256, smem1>>>(x, mask, norm_w, norm_b, wl, bl, wr, br);
    dim3 g2(64, 32);
    k2_opm<<<g2, 256, smem2>>>(mask, bf, out);
}

// round 9
// speedup vs baseline: 1.0547x; 1.0547x over previous
#include <cuda_runtime.h>
#include <cuda_fp16.h>
#include <cstdint>

#define FULL_MASK 0xffffffffu

// scratch (fp16, k-position permuted within 16-groups):
__device__ __half g_Rt[8192 * 256];   // row n*32+y: [hi 128 | lo 128] (m)
__device__ __half g_Lt[8192 * 128];   // row n*32+x: [hi 128] (m)
__device__ __half g_wfT[128 * 2048];  // row o: [hi 1024 | lo 1024] (k)

// ------------------------- helpers -------------------------
__device__ __forceinline__ uint32_t smem_u32(const void *p) {
    uint32_t a;
    asm("{ .reg .u64 t; cvta.to.shared.u64 t, %1; cvt.u32.u64 %0, t; }"
        : "=r"(a) : "l"(p));
    return a;
}
__device__ __forceinline__ void cpa16(uint32_t dst, const void *src) {
    asm volatile("cp.async.ca.shared.global [%0], [%1], 16;"
                 :: "r"(dst), "l"(src));
}
#define CP_COMMIT() asm volatile("cp.async.commit_group;" ::: "memory")
#define CP_WAIT(n) asm volatile("cp.async.wait_group %0;" :: "n"(n) : "memory")

// m16n8k16 f16 with f32 accum. r0 = (a0,a2) [row rb], r1 = (a1,a3) [row rb+8].
__device__ __forceinline__ void mmaf16(float *c, uint2 r0, uint2 r1, uint2 b) {
    asm volatile(
        "mma.sync.aligned.m16n8k16.row.col.f32.f16.f16.f32 "
        "{%0,%1,%2,%3}, {%4,%5,%6,%7}, {%8,%9}, {%0,%1,%2,%3};"
        : "+f"(c[0]), "+f"(c[1]), "+f"(c[2]), "+f"(c[3])
        : "r"(r0.x), "r"(r1.x), "r"(r0.y), "r"(r1.y), "r"(b.x), "r"(b.y));
}

// within-16-group permutation: storage position of local k value kl:
// pos16(kl) = ((kl&7)>>1)*4 + ((kl>>3)&1)*2 + (kl&1)
// -> thread q's 8B load at byte q*8 yields halves k = 2q,2q+1,8+2q,8+2q+1.

// =====================================================================
// Kernel 1: LayerNorm + projections -> g_Lt/g_Rt; blocks<32 also do wf.
// grid = 1024: block b -> mc = b>>8 (m-chunk of 32), n = b&255.
// =====================================================================
__global__ __launch_bounds__(256) void k1_ln_proj(
    const float *__restrict__ x, const float *__restrict__ mask,
    const float *__restrict__ norm_w, const float *__restrict__ norm_b,
    const float *__restrict__ wl, const float *__restrict__ bl,
    const float *__restrict__ wr, const float *__restrict__ br,
    const float *__restrict__ wf) {
    extern __shared__ float sm[];
    __shared__ float Tk[32 * 130];
    float *sw = sm;           // [256][64]
    float *sb = sw + 16384;   // [64]
    float *snw = sb + 64;     // [256]
    float *snb = snw + 256;   // [256]
    float *sxn = snb + 256;   // [32][256] (reused as T[64][36])

    const int t = threadIdx.x;
    for (int idx = t; idx < 16384; idx += 256) {
        int k = idx >> 6, c = idx & 63;
        sw[idx] = (c < 32) ? wl[k * 32 + c] : wr[k * 32 + c - 32];
    }
    if (t < 64) sb[t] = (t < 32) ? bl[t] : br[t - 32];
    snw[t] = norm_w[t];
    snb[t] = norm_b[t];
    __syncthreads();

    const int mc = blockIdx.x >> 8;
    const int n = blockIdx.x & 255;

    {
        const int warp = t >> 5, lane = t & 31;
#pragma unroll
        for (int rr = 0; rr < 4; rr++) {
            const int lrow = warp * 4 + rr;
            const int m = mc * 32 + lrow;
            const float4 *xr = (const float4 *)(x + ((size_t)m * 256 + n) * 256);
            float4 v0 = xr[lane];
            float4 v1 = xr[32 + lane];
            float s1 = v0.x + v0.y + v0.z + v0.w + v1.x + v1.y + v1.z + v1.w;
            float s2 = v0.x * v0.x + v0.y * v0.y + v0.z * v0.z + v0.w * v0.w +
                       v1.x * v1.x + v1.y * v1.y + v1.z * v1.z + v1.w * v1.w;
#pragma unroll
            for (int off = 16; off; off >>= 1) {
                s1 += __shfl_xor_sync(FULL_MASK, s1, off);
                s2 += __shfl_xor_sync(FULL_MASK, s2, off);
            }
            float mu = s1 * (1.f / 256.f);
            float var = s2 * (1.f / 256.f) - mu * mu;
            float inv = rsqrtf(var + 1e-5f);
            int k0 = lane * 4, k1i = 128 + lane * 4;
            float4 n0, n1;
            n0.x = (v0.x - mu) * inv * snw[k0 + 0] + snb[k0 + 0];
            n0.y = (v0.y - mu) * inv * snw[k0 + 1] + snb[k0 + 1];
            n0.z = (v0.z - mu) * inv * snw[k0 + 2] + snb[k0 + 2];
            n0.w = (v0.w - mu) * inv * snw[k0 + 3] + snb[k0 + 3];
            n1.x = (v1.x - mu) * inv * snw[k1i + 0] + snb[k1i + 0];
            n1.y = (v1.y - mu) * inv * snw[k1i + 1] + snb[k1i + 1];
            n1.z = (v1.z - mu) * inv * snw[k1i + 2] + snb[k1i + 2];
            n1.w = (v1.w - mu) * inv * snw[k1i + 3] + snb[k1i + 3];
            ((float4 *)(sxn + lrow * 256))[lane] = n0;
            ((float4 *)(sxn + lrow * 256))[32 + lane] = n1;
        }
    }
    __syncthreads();

    const int tr = t >> 5;
    const int c2 = t & 31;
    float2 acc[4] = {{0, 0}, {0, 0}, {0, 0}, {0, 0}};
    const float *xr0 = sxn + tr * 4 * 256;
#pragma unroll 8
    for (int k = 0; k < 256; k++) {
        float2 wv = *(const float2 *)(sw + k * 64 + c2 * 2);
#pragma unroll
        for (int i = 0; i < 4; i++) {
            float a = xr0[i * 256 + k];
            acc[i].x = fmaf(a, wv.x, acc[i].x);
            acc[i].y = fmaf(a, wv.y, acc[i].y);
        }
    }
    float2 bv = *(const float2 *)(sb + c2 * 2);
    float2 ov[4];
#pragma unroll
    for (int i = 0; i < 4; i++) {
        int m = mc * 32 + tr * 4 + i;
        float mv = mask[m * 256 + n];
        ov[i].x = (acc[i].x + bv.x) * mv;
        ov[i].y = (acc[i].y + bv.y) * mv;
    }
    __syncthreads();
    float *T = sxn;  // [64][36]
    {
        int ch = (c2 < 16) ? (c2 * 2) : (32 + (c2 - 16) * 2);
#pragma unroll
        for (int i = 0; i < 4; i++) {
            int ml = tr * 4 + i;
            T[ch * 36 + ml] = ov[i].x;
            T[(ch + 1) * 36 + ml] = ov[i].y;
        }
    }
    __syncthreads();
    {
        int ch = t >> 2;             // 0..63
        int m0 = (t & 3) * 8;        // 0,8,16,24
        float v[8];
#pragma unroll
        for (int d = 0; d < 8; d++) v[d] = T[ch * 36 + m0 + d];
        int g16 = m0 & ~15;          // 0 or 16
        int sub = (m0 & 8) ? 2 : 0;  // half-offset within 4-slot
        if (ch < 32) {
            __half *base = g_Lt + (size_t)(n * 32 + ch) * 128 + mc * 32;
#pragma unroll
            for (int d2 = 0; d2 < 4; d2++) {
                __half2 h = __halves2half2(__float2half_rn(v[2 * d2]),
                                           __float2half_rn(v[2 * d2 + 1]));
                *(__half2 *)(base + g16 + d2 * 4 + sub) = h;
            }
        } else {
            __half *base = g_Rt + (size_t)(n * 32 + (ch - 32)) * 256 + mc * 32;
#pragma unroll
            for (int d2 = 0; d2 < 4; d2++) {
                float a0 = v[2 * d2], a1 = v[2 * d2 + 1];
                __half h0 = __float2half_rn(a0), h1 = __float2half_rn(a1);
                __half l0 = __float2half_rn(a0 - __half2float(h0));
                __half l1 = __float2half_rn(a1 - __half2float(h1));
                *(__half2 *)(base + g16 + d2 * 4 + sub) = __halves2half2(h0, h1);
                *(__half2 *)(base + 128 + g16 + d2 * 4 + sub) =
                    __halves2half2(l0, l1);
            }
        }
    }

    // ---- wf transpose (blocks 0..31 only): k-chunk b of 32 ----
    if (blockIdx.x < 32) {
        const int b = blockIdx.x;
        __syncthreads();
#pragma unroll
        for (int it = 0; it < 16; it++) {
            int f = t + it * 256;
            int kk = f >> 7, o = f & 127;
            Tk[kk * 130 + o] = wf[(size_t)(b * 32 + kk) * 128 + o];
        }
        __syncthreads();
#pragma unroll
        for (int it = 0; it < 4; it++) {
            int f4 = t + it * 256;       // 0..1023
            int o = f4 >> 3, kq = f4 & 7;
            __half hi[4], lo[4];
#pragma unroll
            for (int j = 0; j < 4; j++) {
                int kl = (j >> 1) * 8 + (kq & 3) * 2 + (j & 1);
                int kk = (kq >> 2) * 16 + kl;
                float wv = Tk[kk * 130 + o];
                hi[j] = __float2half_rn(wv);
                lo[j] = __float2half_rn(wv - __half2float(hi[j]));
            }
            __half *dh = g_wfT + (size_t)o * 2048 + b * 32 + kq * 4;
            *(__half2 *)(dh + 0) = __halves2half2(hi[0], hi[1]);
            *(__half2 *)(dh + 2) = __halves2half2(hi[2], hi[3]);
            *(__half2 *)(dh + 1024) = __halves2half2(lo[0], lo[1]);
            *(__half2 *)(dh + 1026) = __halves2half2(lo[2], lo[3]);
        }
    }
}

// =====================================================================
// Kernel 2: fused outer-product (B) + projection (C), split-fp16 HMMA.
// grid = (64, 32): CTA (bi, bj2): i-block bi (128 ix), j-blocks jb=bj2*2+g.
// smem:
//   0      : snorm[32]
//   1024   : stage B buf0 (R 18432 [144B rows: hi64|lo64|pad] | L 10240
//            [80B rows: hi64|pad]); stage C cbuf0/cbuf1 (wf, 18432 each)
//   29696  : stage B buf1; (cbuf2 at 37888)
//   58368  : S' fp16 [32 p][1024 k] rows 2064B  (66048)
// total 124416
// =====================================================================
#define OFF_SP 58368
#define SP_STRIDE 2064
#define RROW 144
#define LROW 80

__global__ __launch_bounds__(256, 1) void k2_opm(
    const float *__restrict__ mask, const float *__restrict__ bf,
    float *__restrict__ out) {
    extern __shared__ __align__(1024) char smem[];
    const uint32_t sb32 = smem_u32(smem);
    const int t = threadIdx.x, w = t >> 5, lane = t & 31;
    const int rb = lane >> 2, q = lane & 3;
    const int bi = blockIdx.x, bj2 = blockIdx.y;
    float *snorm = (float *)smem;
    const int OA[2] = {1024, 29696};
    const int CB[3] = {1024, 19456, 37888};

    // ---- pair norms ----
    {
        int p = t >> 3, l = t & 7;
        int g = p >> 4, ii = (p >> 2) & 3, jj = p & 3;
        int gi = bi * 4 + ii, gj = (bj2 * 2 + g) * 4 + jj;
        float s = 0.f;
#pragma unroll
        for (int mm = 0; mm < 16; mm++) {
            int m = l + mm * 8;
            s += mask[m * 256 + gi] * mask[m * 256 + gj];
        }
        s += __shfl_down_sync(FULL_MASK, s, 4);
        s += __shfl_down_sync(FULL_MASK, s, 2);
        s += __shfl_down_sync(FULL_MASK, s, 1);
        if (l == 0) snorm[p] = s;
    }

    // ================= Stage B =================
    auto loadB = [&](int buf, int g, int mcv) {
        int jb = bj2 * 2 + g;
        uint32_t dR = sb32 + OA[buf], dL = dR + 18432;
#pragma unroll
        for (int i = 0; i < 4; i++) {   // R: 1024 16B units
            int u = t + i * 256;
            int row = u >> 3, qq = u & 7;
            const __half *src =
                g_Rt + (size_t)(jb * 128 + row) * 256 +
                ((qq < 4) ? (mcv * 32 + qq * 8) : (128 + mcv * 32 + (qq - 4) * 8));
            cpa16(dR + row * RROW + qq * 16, src);
        }
#pragma unroll
        for (int i = 0; i < 2; i++) {   // L: 512 16B units (hi only)
            int u = t + i * 256;
            int row = u >> 2, qq = u & 3;
            cpa16(dL + row * LROW + qq * 16,
                  g_Lt + (size_t)(bi * 128 + row) * 128 + mcv * 32 + qq * 8);
        }
    };

    const int wm = w >> 1, wn = w & 1;  // warp tile: 32 jy x 64 ix
    loadB(0, 0, 0);
    CP_COMMIT();

    for (int g = 0; g < 2; g++) {
        float acc[2][8][4];
#pragma unroll
        for (int a = 0; a < 2; a++)
#pragma unroll
            for (int b = 0; b < 8; b++)
#pragma unroll
                for (int c = 0; c < 4; c++) acc[a][b][c] = 0.f;

        for (int mcv = 0; mcv < 4; mcv++) {
            const int c = g * 4 + mcv, buf = c & 1;
            if (c < 7) {
                int nc = c + 1;
                loadB(nc & 1, nc >> 2, nc & 3);
                CP_COMMIT();
                CP_WAIT(1);
            } else {
                CP_WAIT(0);
            }
            __syncthreads();
            const char *Rb = smem + OA[buf];
            const char *Lb = smem + OA[buf] + 18432;
#pragma unroll
            for (int s = 0; s < 2; s++) {
                uint2 rhi[2][2], rlo[2][2];
#pragma unroll
                for (int mt = 0; mt < 2; mt++) {
                    int r = wm * 32 + mt * 16 + rb;
                    rhi[mt][0] = *(const uint2 *)(Rb + r * RROW + s * 32 + q * 8);
                    rhi[mt][1] =
                        *(const uint2 *)(Rb + (r + 8) * RROW + s * 32 + q * 8);
                    rlo[mt][0] =
                        *(const uint2 *)(Rb + r * RROW + 64 + s * 32 + q * 8);
                    rlo[mt][1] =
                        *(const uint2 *)(Rb + (r + 8) * RROW + 64 + s * 32 + q * 8);
                }
#pragma unroll
                for (int nt = 0; nt < 8; nt++) {
                    int n = wn * 64 + nt * 8 + rb;
                    uint2 bh = *(const uint2 *)(Lb + n * LROW + s * 32 + q * 8);
                    mmaf16(acc[0][nt], rhi[0][0], rhi[0][1], bh);
                    mmaf16(acc[0][nt], rlo[0][0], rlo[0][1], bh);
                    mmaf16(acc[1][nt], rhi[1][0], rhi[1][1], bh);
                    mmaf16(acc[1][nt], rlo[1][0], rlo[1][1], bh);
                }
            }
            __syncthreads();
        }
        // write S'_g as fp16, permuted k positions (thread-private targets)
#pragma unroll
        for (int mt = 0; mt < 2; mt++)
#pragma unroll
            for (int nt = 0; nt < 8; nt++)
#pragma unroll
                for (int cr = 0; cr < 4; cr++) {
                    int jy = wm * 32 + mt * 16 + rb + ((cr >= 2) ? 8 : 0);
                    int ix = wn * 64 + nt * 8 + q * 2 + (cr & 1);
                    int p = g * 16 + (ix >> 5) * 4 + (jy >> 5);
                    int k = (ix & 31) * 32 + (jy & 31);
                    int kl = k & 15;
                    int pos = (k & ~15) + ((kl & 7) >> 1) * 4 +
                              ((kl >> 3) & 1) * 2 + (kl & 1);
                    *(__half *)(smem + OFF_SP + p * SP_STRIDE + pos * 2) =
                        __float2half_rn(acc[mt][nt][cr]);
                }
    }
    __syncthreads();  // S' complete; stage-B bufs fully consumed

    // ================= Stage C =================
    auto loadC = [&](int buf, int ct) {
        uint32_t dA = sb32 + CB[buf];
#pragma unroll
        for (int i = 0; i < 4; i++) {   // 1024 16B units (4 hi + 4 lo per row)
            int u = t + i * 256;
            int row = u >> 3, qq = u & 7;
            const __half *src =
                g_wfT + (size_t)row * 2048 +
                ((qq < 4) ? (ct * 32 + qq * 8) : (1024 + ct * 32 + (qq - 4) * 8));
            cpa16(dA + row * RROW + qq * 16, src);
        }
    };

    loadC(0, 0);
    CP_COMMIT();
    loadC(1, 1);
    CP_COMMIT();

    float cc[4][4];
#pragma unroll
    for (int a = 0; a < 4; a++)
#pragma unroll
        for (int b = 0; b < 4; b++) cc[a][b] = 0.f;

    for (int ct = 0; ct < 32; ct++) {
        const int buf = ct - (ct / 3) * 3;  // ct % 3
        if (ct + 2 < 32) {
            int nb = (ct + 2) - ((ct + 2) / 3) * 3;
            loadC(nb, ct + 2);
            CP_COMMIT();
            CP_WAIT(2);
        } else if (ct + 1 < 32) {
            CP_WAIT(1);
        } else {
            CP_WAIT(0);
        }
        __syncthreads();  // buf ready; all warps done with ct-1
        const char *A = smem + CB[buf];
#pragma unroll
        for (int s = 0; s < 2; s++) {
            int r = w * 16 + rb;
            uint2 whi0 = *(const uint2 *)(A + r * RROW + s * 32 + q * 8);
            uint2 whi1 = *(const uint2 *)(A + (r + 8) * RROW + s * 32 + q * 8);
            uint2 wlo0 = *(const uint2 *)(A + r * RROW + 64 + s * 32 + q * 8);
            uint2 wlo1 = *(const uint2 *)(A + (r + 8) * RROW + 64 + s * 32 + q * 8);
#pragma unroll
            for (int nt = 0; nt < 4; nt++) {
                int p = nt * 8 + rb;
                uint2 bh = *(const uint2 *)(smem + OFF_SP + p * SP_STRIDE +
                                            (ct * 32 + s * 16) * 2 + q * 8);
                mmaf16(cc[nt], whi0, whi1, bh);
                mmaf16(cc[nt], wlo0, wlo1, bh);
            }
        }
        __syncthreads();
    }

    // ---- epilogue: stage through smem, bias + norm, coalesced store ----
    float *sOut = (float *)(smem + CB[0]);  // [32 p][128 o]
#pragma unroll
    for (int nt = 0; nt < 4; nt++)
#pragma unroll
        for (int cr = 0; cr < 4; cr++) {
            int o = w * 16 + rb + ((cr >= 2) ? 8 : 0);
            int p = nt * 8 + q * 2 + (cr & 1);
            sOut[p * 128 + o] = cc[nt][cr];
        }
    __syncthreads();
#pragma unroll
    for (int i = 0; i < 4; i++) {
        int u = t + i * 256;          // float4 unit 0..1023
        int p = u >> 5, o4 = (u & 31) * 4;
        int g = p >> 4, iiv = (p >> 2) & 3, jjv = p & 3;
        int gi = bi * 4 + iiv, gj = (bj2 * 2 + g) * 4 + jjv;
        float inv = 1.f / (snorm[p] + 0.001f);
        float4 v = *(float4 *)(sOut + p * 128 + o4);
        float4 bb = *(const float4 *)(bf + o4);
        v.x = (v.x + bb.x) * inv;
        v.y = (v.y + bb.y) * inv;
        v.z = (v.z + bb.z) * inv;
        v.w = (v.w + bb.w) * inv;
        *(float4 *)(out + ((size_t)gi * 256 + gj) * 128 + o4) = v;
    }
}

// =====================================================================
extern "C" void kernel_launch(void *const *d_in, const int *in_sizes, int n_in,
                              void *d_out, int out_size) {
    const float *x = (const float *)d_in[0];
    const float *mask = (const float *)d_in[1];
    const float *norm_w = (const float *)d_in[2];
    const float *norm_b = (const float *)d_in[3];
    const float *wl = (const float *)d_in[4];
    const float *bl = (const float *)d_in[5];
    const float *wr = (const float *)d_in[6];
    const float *br = (const float *)d_in[7];
    const float *wf = (const float *)d_in[8];
    const float *bf = (const float *)d_in[9];
    float *out = (float *)d_out;

    const int smem1 = (16384 + 64 + 256 + 256 + 8192) * 4;  // 100608 B
    const int smem2 = 124416;
    cudaFuncSetAttribute(k1_ln_proj, cudaFuncAttributeMaxDynamicSharedMemorySize, smem1);
    cudaFuncSetAttribute(k2_opm, cudaFuncAttributeMaxDynamicSharedMemorySize, smem2);

    k1_ln_proj<<<1024, 256, smem1>>>(x, mask, norm_w, norm_b, wl, bl, wr, br, wf);
    dim3 g2(64, 32);
    k2_opm<<<g2, 256, smem2>>>(mask, bf, out);
}

// round 10
// speedup vs baseline: 1.0581x; 1.0033x over previous
#include <cuda_runtime.h>
#include <cuda_fp16.h>
#include <cstdint>

#define FULL_MASK 0xffffffffu

// scratch (fp16, k-position permuted within 16-groups):
__device__ __half g_Rt[8192 * 256];   // row n*32+y: [hi 128 | lo 128] (m)
__device__ __half g_Lt[8192 * 128];   // row n*32+x: [hi 128] (m)
__device__ __half g_wfT[128 * 2048];  // row o: [hi 1024 | lo 1024] (k)

// ------------------------- helpers -------------------------
__device__ __forceinline__ uint32_t smem_u32(const void *p) {
    uint32_t a;
    asm("{ .reg .u64 t; cvta.to.shared.u64 t, %1; cvt.u32.u64 %0, t; }"
        : "=r"(a) : "l"(p));
    return a;
}
__device__ __forceinline__ void cpa16(uint32_t dst, const void *src) {
    asm volatile("cp.async.ca.shared.global [%0], [%1], 16;"
                 :: "r"(dst), "l"(src));
}
#define CP_COMMIT() asm volatile("cp.async.commit_group;" ::: "memory")
#define CP_WAIT(n) asm volatile("cp.async.wait_group %0;" :: "n"(n) : "memory")

// m16n8k16 f16 with f32 accum. r0 = (a0,a2) [row rb], r1 = (a1,a3) [row rb+8].
__device__ __forceinline__ void mmaf16(float *c, uint2 r0, uint2 r1, uint2 b) {
    asm volatile(
        "mma.sync.aligned.m16n8k16.row.col.f32.f16.f16.f32 "
        "{%0,%1,%2,%3}, {%4,%5,%6,%7}, {%8,%9}, {%0,%1,%2,%3};"
        : "+f"(c[0]), "+f"(c[1]), "+f"(c[2]), "+f"(c[3])
        : "r"(r0.x), "r"(r1.x), "r"(r0.y), "r"(r1.y), "r"(b.x), "r"(b.y));
}

// within-16-group permutation: storage position of local k value kl:
// pos16(kl) = ((kl&7)>>1)*4 + ((kl>>3)&1)*2 + (kl&1)
// -> thread q's 8B load at byte q*8 yields halves k = 2q,2q+1,8+2q,8+2q+1.

// =====================================================================
// Kernel 1: LayerNorm + projections -> g_Lt/g_Rt; blocks<32 also do wf.
// grid = 1024: block b -> mc = b>>8 (m-chunk of 32), n = b&255.
// =====================================================================
__global__ __launch_bounds__(256) void k1_ln_proj(
    const float *__restrict__ x, const float *__restrict__ mask,
    const float *__restrict__ norm_w, const float *__restrict__ norm_b,
    const float *__restrict__ wl, const float *__restrict__ bl,
    const float *__restrict__ wr, const float *__restrict__ br,
    const float *__restrict__ wf) {
    extern __shared__ float sm[];
    __shared__ float Tk[32 * 130];
    float *sw = sm;           // [256][64]
    float *sb = sw + 16384;   // [64]
    float *snw = sb + 64;     // [256]
    float *snb = snw + 256;   // [256]
    float *sxn = snb + 256;   // [32][256] (reused as T[64][36])

    const int t = threadIdx.x;
    for (int idx = t; idx < 16384; idx += 256) {
        int k = idx >> 6, c = idx & 63;
        sw[idx] = (c < 32) ? wl[k * 32 + c] : wr[k * 32 + c - 32];
    }
    if (t < 64) sb[t] = (t < 32) ? bl[t] : br[t - 32];
    snw[t] = norm_w[t];
    snb[t] = norm_b[t];
    __syncthreads();

    const int mc = blockIdx.x >> 8;
    const int n = blockIdx.x & 255;

    {
        const int warp = t >> 5, lane = t & 31;
#pragma unroll
        for (int rr = 0; rr < 4; rr++) {
            const int lrow = warp * 4 + rr;
            const int m = mc * 32 + lrow;
            const float4 *xr = (const float4 *)(x + ((size_t)m * 256 + n) * 256);
            float4 v0 = xr[lane];
            float4 v1 = xr[32 + lane];
            float s1 = v0.x + v0.y + v0.z + v0.w + v1.x + v1.y + v1.z + v1.w;
            float s2 = v0.x * v0.x + v0.y * v0.y + v0.z * v0.z + v0.w * v0.w +
                       v1.x * v1.x + v1.y * v1.y + v1.z * v1.z + v1.w * v1.w;
#pragma unroll
            for (int off = 16; off; off >>= 1) {
                s1 += __shfl_xor_sync(FULL_MASK, s1, off);
                s2 += __shfl_xor_sync(FULL_MASK, s2, off);
            }
            float mu = s1 * (1.f / 256.f);
            float var = s2 * (1.f / 256.f) - mu * mu;
            float inv = rsqrtf(var + 1e-5f);
            int k0 = lane * 4, k1i = 128 + lane * 4;
            float4 n0, n1;
            n0.x = (v0.x - mu) * inv * snw[k0 + 0] + snb[k0 + 0];
            n0.y = (v0.y - mu) * inv * snw[k0 + 1] + snb[k0 + 1];
            n0.z = (v0.z - mu) * inv * snw[k0 + 2] + snb[k0 + 2];
            n0.w = (v0.w - mu) * inv * snw[k0 + 3] + snb[k0 + 3];
            n1.x = (v1.x - mu) * inv * snw[k1i + 0] + snb[k1i + 0];
            n1.y = (v1.y - mu) * inv * snw[k1i + 1] + snb[k1i + 1];
            n1.z = (v1.z - mu) * inv * snw[k1i + 2] + snb[k1i + 2];
            n1.w = (v1.w - mu) * inv * snw[k1i + 3] + snb[k1i + 3];
            ((float4 *)(sxn + lrow * 256))[lane] = n0;
            ((float4 *)(sxn + lrow * 256))[32 + lane] = n1;
        }
    }
    __syncthreads();

    const int tr = t >> 5;
    const int c2 = t & 31;
    float2 acc[4] = {{0, 0}, {0, 0}, {0, 0}, {0, 0}};
    const float *xr0 = sxn + tr * 4 * 256;
#pragma unroll 8
    for (int k = 0; k < 256; k++) {
        float2 wv = *(const float2 *)(sw + k * 64 + c2 * 2);
#pragma unroll
        for (int i = 0; i < 4; i++) {
            float a = xr0[i * 256 + k];
            acc[i].x = fmaf(a, wv.x, acc[i].x);
            acc[i].y = fmaf(a, wv.y, acc[i].y);
        }
    }
    float2 bv = *(const float2 *)(sb + c2 * 2);
    float2 ov[4];
#pragma unroll
    for (int i = 0; i < 4; i++) {
        int m = mc * 32 + tr * 4 + i;
        float mv = mask[m * 256 + n];
        ov[i].x = (acc[i].x + bv.x) * mv;
        ov[i].y = (acc[i].y + bv.y) * mv;
    }
    __syncthreads();
    float *T = sxn;  // [64][36]
    {
        int ch = (c2 < 16) ? (c2 * 2) : (32 + (c2 - 16) * 2);
#pragma unroll
        for (int i = 0; i < 4; i++) {
            int ml = tr * 4 + i;
            T[ch * 36 + ml] = ov[i].x;
            T[(ch + 1) * 36 + ml] = ov[i].y;
        }
    }
    __syncthreads();
    {
        int ch = t >> 2;             // 0..63
        int m0 = (t & 3) * 8;        // 0,8,16,24
        float v[8];
#pragma unroll
        for (int d = 0; d < 8; d++) v[d] = T[ch * 36 + m0 + d];
        int g16 = m0 & ~15;          // 0 or 16
        int sub = (m0 & 8) ? 2 : 0;  // half-offset within 4-slot
        if (ch < 32) {
            __half *base = g_Lt + (size_t)(n * 32 + ch) * 128 + mc * 32;
#pragma unroll
            for (int d2 = 0; d2 < 4; d2++) {
                __half2 h = __halves2half2(__float2half_rn(v[2 * d2]),
                                           __float2half_rn(v[2 * d2 + 1]));
                *(__half2 *)(base + g16 + d2 * 4 + sub) = h;
            }
        } else {
            __half *base = g_Rt + (size_t)(n * 32 + (ch - 32)) * 256 + mc * 32;
#pragma unroll
            for (int d2 = 0; d2 < 4; d2++) {
                float a0 = v[2 * d2], a1 = v[2 * d2 + 1];
                __half h0 = __float2half_rn(a0), h1 = __float2half_rn(a1);
                __half l0 = __float2half_rn(a0 - __half2float(h0));
                __half l1 = __float2half_rn(a1 - __half2float(h1));
                *(__half2 *)(base + g16 + d2 * 4 + sub) = __halves2half2(h0, h1);
                *(__half2 *)(base + 128 + g16 + d2 * 4 + sub) =
                    __halves2half2(l0, l1);
            }
        }
    }

    // ---- wf transpose (blocks 0..31 only): k-chunk b of 32 ----
    if (blockIdx.x < 32) {
        const int b = blockIdx.x;
        __syncthreads();
#pragma unroll
        for (int it = 0; it < 16; it++) {
            int f = t + it * 256;
            int kk = f >> 7, o = f & 127;
            Tk[kk * 130 + o] = wf[(size_t)(b * 32 + kk) * 128 + o];
        }
        __syncthreads();
#pragma unroll
        for (int it = 0; it < 4; it++) {
            int f4 = t + it * 256;       // 0..1023
            int o = f4 >> 3, kq = f4 & 7;
            __half hi[4], lo[4];
#pragma unroll
            for (int j = 0; j < 4; j++) {
                int kl = (j >> 1) * 8 + (kq & 3) * 2 + (j & 1);
                int kk = (kq >> 2) * 16 + kl;
                float wv = Tk[kk * 130 + o];
                hi[j] = __float2half_rn(wv);
                lo[j] = __float2half_rn(wv - __half2float(hi[j]));
            }
            __half *dh = g_wfT + (size_t)o * 2048 + b * 32 + kq * 4;
            *(__half2 *)(dh + 0) = __halves2half2(hi[0], hi[1]);
            *(__half2 *)(dh + 2) = __halves2half2(hi[2], hi[3]);
            *(__half2 *)(dh + 1024) = __halves2half2(lo[0], lo[1]);
            *(__half2 *)(dh + 1026) = __halves2half2(lo[2], lo[3]);
        }
    }
}

// =====================================================================
// Kernel 2: fused outer-product (B) + projection (C), split-fp16 HMMA.
// grid = (64, 32): CTA (bi, bj2): i-block bi (128 ix), j-blocks jb=bj2*2+g.
// smem:
//   0      : snorm[32]
//   1024   : stage B buf0 (R 18432 [144B rows: hi64|lo64|pad] | L 10240
//            [80B rows: hi64|pad]); stage C cbuf0/cbuf1 (wf, 18432 each)
//   29696  : stage B buf1; (cbuf2 at 37888)
//   58368  : S' fp16 [32 p][1024 k] rows 2064B  (66048)
// total 124416
// =====================================================================
#define OFF_SP 58368
#define SP_STRIDE 2064
#define RROW 144
#define LROW 80

__global__ __launch_bounds__(256, 1) void k2_opm(
    const float *__restrict__ mask, const float *__restrict__ bf,
    float *__restrict__ out) {
    extern __shared__ __align__(1024) char smem[];
    const uint32_t sb32 = smem_u32(smem);
    const int t = threadIdx.x, w = t >> 5, lane = t & 31;
    const int rb = lane >> 2, q = lane & 3;
    const int bi = blockIdx.x, bj2 = blockIdx.y;
    float *snorm = (float *)smem;
    const int OA[2] = {1024, 29696};
    const int CB[3] = {1024, 19456, 37888};

    // ---- pair norms ----
    {
        int p = t >> 3, l = t & 7;
        int g = p >> 4, ii = (p >> 2) & 3, jj = p & 3;
        int gi = bi * 4 + ii, gj = (bj2 * 2 + g) * 4 + jj;
        float s = 0.f;
#pragma unroll
        for (int mm = 0; mm < 16; mm++) {
            int m = l + mm * 8;
            s += mask[m * 256 + gi] * mask[m * 256 + gj];
        }
        s += __shfl_down_sync(FULL_MASK, s, 4);
        s += __shfl_down_sync(FULL_MASK, s, 2);
        s += __shfl_down_sync(FULL_MASK, s, 1);
        if (l == 0) snorm[p] = s;
    }

    // ================= Stage B =================
    auto loadB = [&](int buf, int g, int mcv) {
        int jb = bj2 * 2 + g;
        uint32_t dR = sb32 + OA[buf], dL = dR + 18432;
#pragma unroll
        for (int i = 0; i < 4; i++) {   // R: 1024 16B units
            int u = t + i * 256;
            int row = u >> 3, qq = u & 7;
            const __half *src =
                g_Rt + (size_t)(jb * 128 + row) * 256 +
                ((qq < 4) ? (mcv * 32 + qq * 8) : (128 + mcv * 32 + (qq - 4) * 8));
            cpa16(dR + row * RROW + qq * 16, src);
        }
#pragma unroll
        for (int i = 0; i < 2; i++) {   // L: 512 16B units (hi only)
            int u = t + i * 256;
            int row = u >> 2, qq = u & 3;
            cpa16(dL + row * LROW + qq * 16,
                  g_Lt + (size_t)(bi * 128 + row) * 128 + mcv * 32 + qq * 8);
        }
    };

    const int wm = w >> 1, wn = w & 1;  // warp tile: 32 jy x 64 ix
    loadB(0, 0, 0);
    CP_COMMIT();

    for (int g = 0; g < 2; g++) {
        float acc[2][8][4];
#pragma unroll
        for (int a = 0; a < 2; a++)
#pragma unroll
            for (int b = 0; b < 8; b++)
#pragma unroll
                for (int c = 0; c < 4; c++) acc[a][b][c] = 0.f;

        for (int mcv = 0; mcv < 4; mcv++) {
            const int c = g * 4 + mcv, buf = c & 1;
            if (c < 7) {
                int nc = c + 1;
                loadB(nc & 1, nc >> 2, nc & 3);
                CP_COMMIT();
                CP_WAIT(1);
            } else {
                CP_WAIT(0);
            }
            __syncthreads();
            const char *Rb = smem + OA[buf];
            const char *Lb = smem + OA[buf] + 18432;
#pragma unroll
            for (int s = 0; s < 2; s++) {
                uint2 rhi[2][2], rlo[2][2];
#pragma unroll
                for (int mt = 0; mt < 2; mt++) {
                    int r = wm * 32 + mt * 16 + rb;
                    rhi[mt][0] = *(const uint2 *)(Rb + r * RROW + s * 32 + q * 8);
                    rhi[mt][1] =
                        *(const uint2 *)(Rb + (r + 8) * RROW + s * 32 + q * 8);
                    rlo[mt][0] =
                        *(const uint2 *)(Rb + r * RROW + 64 + s * 32 + q * 8);
                    rlo[mt][1] =
                        *(const uint2 *)(Rb + (r + 8) * RROW + 64 + s * 32 + q * 8);
                }
#pragma unroll
                for (int nt = 0; nt < 8; nt++) {
                    int n = wn * 64 + nt * 8 + rb;
                    uint2 bh = *(const uint2 *)(Lb + n * LROW + s * 32 + q * 8);
                    mmaf16(acc[0][nt], rhi[0][0], rhi[0][1], bh);
                    mmaf16(acc[0][nt], rlo[0][0], rlo[0][1], bh);
                    mmaf16(acc[1][nt], rhi[1][0], rhi[1][1], bh);
                    mmaf16(acc[1][nt], rlo[1][0], rlo[1][1], bh);
                }
            }
            __syncthreads();
        }
        // write S'_g as fp16, permuted k positions (thread-private targets)
#pragma unroll
        for (int mt = 0; mt < 2; mt++)
#pragma unroll
            for (int nt = 0; nt < 8; nt++)
#pragma unroll
                for (int cr = 0; cr < 4; cr++) {
                    int jy = wm * 32 + mt * 16 + rb + ((cr >= 2) ? 8 : 0);
                    int ix = wn * 64 + nt * 8 + q * 2 + (cr & 1);
                    int p = g * 16 + (ix >> 5) * 4 + (jy >> 5);
                    int k = (ix & 31) * 32 + (jy & 31);
                    int kl = k & 15;
                    int pos = (k & ~15) + ((kl & 7) >> 1) * 4 +
                              ((kl >> 3) & 1) * 2 + (kl & 1);
                    *(__half *)(smem + OFF_SP + p * SP_STRIDE + pos * 2) =
                        __float2half_rn(acc[mt][nt][cr]);
                }
    }
    __syncthreads();  // S' complete; stage-B bufs fully consumed

    // ================= Stage C =================
    auto loadC = [&](int buf, int ct) {
        uint32_t dA = sb32 + CB[buf];
#pragma unroll
        for (int i = 0; i < 4; i++) {   // 1024 16B units (4 hi + 4 lo per row)
            int u = t + i * 256;
            int row = u >> 3, qq = u & 7;
            const __half *src =
                g_wfT + (size_t)row * 2048 +
                ((qq < 4) ? (ct * 32 + qq * 8) : (1024 + ct * 32 + (qq - 4) * 8));
            cpa16(dA + row * RROW + qq * 16, src);
        }
    };

    loadC(0, 0);
    CP_COMMIT();
    loadC(1, 1);
    CP_COMMIT();

    float cc[4][4];
#pragma unroll
    for (int a = 0; a < 4; a++)
#pragma unroll
        for (int b = 0; b < 4; b++) cc[a][b] = 0.f;

    for (int ct = 0; ct < 32; ct++) {
        const int buf = ct - (ct / 3) * 3;  // ct % 3
        if (ct + 2 < 32) {
            int nb = (ct + 2) - ((ct + 2) / 3) * 3;
            loadC(nb, ct + 2);
            CP_COMMIT();
            CP_WAIT(2);
        } else if (ct + 1 < 32) {
            CP_WAIT(1);
        } else {
            CP_WAIT(0);
        }
        __syncthreads();  // buf ready; all warps done with ct-1
        const char *A = smem + CB[buf];
#pragma unroll
        for (int s = 0; s < 2; s++) {
            int r = w * 16 + rb;
            uint2 whi0 = *(const uint2 *)(A + r * RROW + s * 32 + q * 8);
            uint2 whi1 = *(const uint2 *)(A + (r + 8) * RROW + s * 32 + q * 8);
            uint2 wlo0 = *(const uint2 *)(A + r * RROW + 64 + s * 32 + q * 8);
            uint2 wlo1 = *(const uint2 *)(A + (r + 8) * RROW + 64 + s * 32 + q * 8);
#pragma unroll
            for (int nt = 0; nt < 4; nt++) {
                int p = nt * 8 + rb;
                uint2 bh = *(const uint2 *)(smem + OFF_SP + p * SP_STRIDE +
                                            (ct * 32 + s * 16) * 2 + q * 8);
                mmaf16(cc[nt], whi0, whi1, bh);
                mmaf16(cc[nt], wlo0, wlo1, bh);
            }
        }
        __syncthreads();
    }

    // ---- epilogue: stage through smem, bias + norm, coalesced store ----
    float *sOut = (float *)(smem + CB[0]);  // [32 p][128 o]
#pragma unroll
    for (int nt = 0; nt < 4; nt++)
#pragma unroll
        for (int cr = 0; cr < 4; cr++) {
            int o = w * 16 + rb + ((cr >= 2) ? 8 : 0);
            int p = nt * 8 + q * 2 + (cr & 1);
            sOut[p * 128 + o] = cc[nt][cr];
        }
    __syncthreads();
#pragma unroll
    for (int i = 0; i < 4; i++) {
        int u = t + i * 256;          // float4 unit 0..1023
        int p = u >> 5, o4 = (u & 31) * 4;
        int g = p >> 4, iiv = (p >> 2) & 3, jjv = p & 3;
        int gi = bi * 4 + iiv, gj = (bj2 * 2 + g) * 4 + jjv;
        float inv = 1.f / (snorm[p] + 0.001f);
        float4 v = *(float4 *)(sOut + p * 128 + o4);
        float4 bb = *(const float4 *)(bf + o4);
        v.x = (v.x + bb.x) * inv;
        v.y = (v.y + bb.y) * inv;
        v.z = (v.z + bb.z) * inv;
        v.w = (v.w + bb.w) * inv;
        *(float4 *)(out + ((size_t)gi * 256 + gj) * 128 + o4) = v;
    }
}

// =====================================================================
extern "C" void kernel_launch(void *const *d_in, const int *in_sizes, int n_in,
                              void *d_out, int out_size) {
    const float *x = (const float *)d_in[0];
    const float *mask = (const float *)d_in[1];
    const float *norm_w = (const float *)d_in[2];
    const float *norm_b = (const float *)d_in[3];
    const float *wl = (const float *)d_in[4];
    const float *bl = (const float *)d_in[5];
    const float *wr = (const float *)d_in[6];
    const float *br = (const float *)d_in[7];
    const float *wf = (const float *)d_in[8];
    const float *bf = (const float *)d_in[9];
    float *out = (float *)d_out;

    const int smem1 = (16384 + 64 + 256 + 256 + 8192) * 4;  // 100608 B
    const int smem2 = 124416;
    cudaFuncSetAttribute(k1_ln_proj, cudaFuncAttributeMaxDynamicSharedMemorySize, smem1);
    cudaFuncSetAttribute(k2_opm, cudaFuncAttributeMaxDynamicSharedMemorySize, smem2);

    k1_ln_proj<<<1024, 256, smem1>>>(x, mask, norm_w, norm_b, wl, bl, wr, br, wf);
    dim3 g2(64, 32);
    k2_opm<<<g2, 256, smem2>>>(mask, bf, out);
}